// round 5
// baseline (speedup 1.0000x reference)
#include <cuda_runtime.h>
#include <math.h>
#include <stdint.h>

// Scratch (static device arrays — no allocation allowed)
#define NMAX 100000
#define DIM  64
__device__ float g_u [NMAX * DIM];   // x @ W1a + b1   (src half of edge MLP layer 1)
__device__ float g_v [NMAX * DIM];   // x @ W1b        (dst half)
__device__ float g_xt[NMAX * DIM];   // x @ wt + bt    (node transform)

// ---------------------------------------------------------------------------
// Zero the node-output region (d_out is poisoned with 0xAA).
// ---------------------------------------------------------------------------
__global__ void zero_kernel(float4* __restrict__ out, int n4) {
    int i = blockIdx.x * blockDim.x + threadIdx.x;
    int stride = gridDim.x * blockDim.x;
    float4 z = make_float4(0.f, 0.f, 0.f, 0.f);
    for (; i < n4; i += stride) out[i] = z;
}

// ---------------------------------------------------------------------------
// Per-node precompute: u = x@W1a + b1, v = x@W1b, xt = x@wt + bt
// Warp per NP nodes; weights staged in shared. Each lane owns output cols
// (2*lane, 2*lane+1) of all three 64x64 transforms.
// ---------------------------------------------------------------------------
__global__ void node_kernel(const float* __restrict__ x,
                            const float* __restrict__ w1,
                            const float* __restrict__ b1,
                            const float* __restrict__ wt,
                            const float* __restrict__ bt,
                            int N) {
    __shared__ float sA[DIM * DIM];   // w1 rows 0..63
    __shared__ float sB[DIM * DIM];   // w1 rows 64..127
    __shared__ float sT[DIM * DIM];   // wt
    __shared__ float sb1[DIM], sbt[DIM];

    int tid = threadIdx.x;
    for (int i = tid; i < DIM * DIM; i += blockDim.x) {
        sA[i] = w1[i];
        sB[i] = w1[DIM * DIM + i];
        sT[i] = wt[i];
    }
    if (tid < DIM) { sb1[tid] = b1[tid]; sbt[tid] = bt[tid]; }
    __syncthreads();

    const int lane   = tid & 31;
    const int warp   = (blockIdx.x * blockDim.x + tid) >> 5;
    const int nwarps = (gridDim.x * blockDim.x) >> 5;
    const int NP = 4;   // nodes per warp pass (amortize the weight LDS)

    float2 bb1 = *(const float2*)&sb1[2 * lane];
    float2 bbt = *(const float2*)&sbt[2 * lane];

    for (int n0 = warp * NP; n0 < N; n0 += nwarps * NP) {
        int cnt = N - n0; if (cnt > NP) cnt = NP;

        float xa[NP], xb[NP];
        #pragma unroll
        for (int j = 0; j < NP; j++) {
            int n = n0 + j;
            if (j < cnt) {
                xa[j] = x[(size_t)n * DIM + lane];
                xb[j] = x[(size_t)n * DIM + 32 + lane];
            } else { xa[j] = 0.f; xb[j] = 0.f; }
        }

        float2 au[NP], av[NP], at[NP];
        #pragma unroll
        for (int j = 0; j < NP; j++) {
            au[j] = bb1;
            av[j] = make_float2(0.f, 0.f);
            at[j] = bbt;
        }

        #pragma unroll 4
        for (int k = 0; k < DIM; k++) {
            float2 wa = *(const float2*)&sA[k * DIM + 2 * lane];
            float2 wb = *(const float2*)&sB[k * DIM + 2 * lane];
            float2 wt2 = *(const float2*)&sT[k * DIM + 2 * lane];
            #pragma unroll
            for (int j = 0; j < NP; j++) {
                float xk = (k < 32) ? __shfl_sync(0xffffffffu, xa[j], k)
                                    : __shfl_sync(0xffffffffu, xb[j], k - 32);
                au[j].x = fmaf(xk, wa.x,  au[j].x);
                au[j].y = fmaf(xk, wa.y,  au[j].y);
                av[j].x = fmaf(xk, wb.x,  av[j].x);
                av[j].y = fmaf(xk, wb.y,  av[j].y);
                at[j].x = fmaf(xk, wt2.x, at[j].x);
                at[j].y = fmaf(xk, wt2.y, at[j].y);
            }
        }

        #pragma unroll
        for (int j = 0; j < NP; j++) {
            if (j < cnt) {
                size_t base = (size_t)(n0 + j) * DIM + 2 * lane;
                *(float2*)&g_u [base] = au[j];
                *(float2*)&g_v [base] = av[j];
                *(float2*)&g_xt[base] = at[j];
            }
        }
    }
}

// ---------------------------------------------------------------------------
// Per-edge: h = relu(u[src] + v[dst] + len*w1c), w = sigmoid(h.w2 + b2),
//           out[dst] += xt[src] * w  (atomic), ew[e] = w.
// One warp per edge; lane owns cols (2*lane, 2*lane+1).
// edge_index is int32 (JAX default x64-disabled coerces int64 -> int32).
// ---------------------------------------------------------------------------
__global__ void edge_kernel(const int* __restrict__ ei,
                            const float* __restrict__ pos,
                            const float* __restrict__ w1,
                            const float* __restrict__ w2,
                            const float* __restrict__ b2p,
                            float* __restrict__ out,
                            float* __restrict__ ew,
                            int E) {
    const int lane   = threadIdx.x & 31;
    const int warp   = (blockIdx.x * blockDim.x + threadIdx.x) >> 5;
    const int nwarps = (gridDim.x * blockDim.x) >> 5;

    // per-lane constants
    const float2 wc  = *(const float2*)&w1[128 * DIM + 2 * lane]; // w1 row 128 (edge_length)
    const float2 w2v = *(const float2*)&w2[2 * lane];
    const float  b2  = b2p[0];

    for (int e = warp; e < E; e += nwarps) {
        int s = ei[e];
        int d = ei[E + e];

        float dx = pos[d * 3 + 0] - pos[s * 3 + 0];
        float dy = pos[d * 3 + 1] - pos[s * 3 + 1];
        float dz = pos[d * 3 + 2] - pos[s * 3 + 2];
        float len = sqrtf(dx * dx + dy * dy + dz * dz);

        const float2 uu = *(const float2*)&g_u[(size_t)s * DIM + 2 * lane];
        const float2 vv = *(const float2*)&g_v[(size_t)d * DIM + 2 * lane];

        float h0 = fmaxf(fmaf(len, wc.x, uu.x + vv.x), 0.f);
        float h1 = fmaxf(fmaf(len, wc.y, uu.y + vv.y), 0.f);
        float p  = fmaf(h0, w2v.x, h1 * w2v.y);

        #pragma unroll
        for (int o = 16; o > 0; o >>= 1)
            p += __shfl_xor_sync(0xffffffffu, p, o);

        float w = 1.f / (1.f + __expf(-(p + b2)));

        if (lane == 0 && ew) ew[e] = w;

        const float2 m = *(const float2*)&g_xt[(size_t)s * DIM + 2 * lane];
        float* o0 = &out[(size_t)d * DIM + 2 * lane];
        atomicAdd(o0,     m.x * w);
        atomicAdd(o0 + 1, m.y * w);
    }
}

// ---------------------------------------------------------------------------
extern "C" void kernel_launch(void* const* d_in, const int* in_sizes, int n_in,
                              void* d_out, int out_size) {
    const float* x   = (const float*)d_in[0];
    const int*   ei  = (const int*)d_in[1];    // int32 (JAX x64 disabled)
    const float* pos = (const float*)d_in[2];
    const float* w1  = (const float*)d_in[3];
    const float* b1  = (const float*)d_in[4];
    const float* w2  = (const float*)d_in[5];
    const float* b2  = (const float*)d_in[6];
    const float* wt  = (const float*)d_in[7];
    const float* bt  = (const float*)d_in[8];

    int N = in_sizes[0] / DIM;   // 100000
    int E = in_sizes[1] / 2;     // 1600000

    float* out = (float*)d_out;
    // Output layout: node output [N*64] followed by edge_weights [E]
    float* ew = (out_size >= N * DIM + E) ? out + (size_t)N * DIM : nullptr;

    zero_kernel<<<256, 256>>>((float4*)out, N * DIM / 4);
    node_kernel<<<592, 256>>>(x, w1, b1, wt, bt, N);
    edge_kernel<<<2368, 256>>>(ei, pos, w1, w2, b2, out, ew, E);
}

// round 6
// speedup vs baseline: 1.3886x; 1.3886x over previous
#include <cuda_runtime.h>
#include <math.h>
#include <stdint.h>

// Scratch (static device arrays — no allocation allowed)
#define NMAX 100000
#define DIM  64
__device__ float g_u [NMAX * DIM];   // x @ W1a + b1   (src half of edge MLP layer 1)
__device__ float g_v [NMAX * DIM];   // x @ W1b        (dst half)
__device__ float g_xt[NMAX * DIM];   // x @ wt + bt    (node transform)

// ---------------------------------------------------------------------------
// Zero the node-output region (d_out is poisoned with 0xAA).
// ---------------------------------------------------------------------------
__global__ void zero_kernel(float4* __restrict__ out, int n4) {
    int i = blockIdx.x * blockDim.x + threadIdx.x;
    int stride = gridDim.x * blockDim.x;
    float4 z = make_float4(0.f, 0.f, 0.f, 0.f);
    for (; i < n4; i += stride) out[i] = z;
}

// ---------------------------------------------------------------------------
// Per-node precompute: u = x@W1a + b1, v = x@W1b, xt = x@wt + bt
// Warp per NP nodes; weights staged in shared. Each lane owns output cols
// (2*lane, 2*lane+1) of all three 64x64 transforms.
// ---------------------------------------------------------------------------
__global__ void node_kernel(const float* __restrict__ x,
                            const float* __restrict__ w1,
                            const float* __restrict__ b1,
                            const float* __restrict__ wt,
                            const float* __restrict__ bt,
                            int N) {
    __shared__ float sA[DIM * DIM];   // w1 rows 0..63
    __shared__ float sB[DIM * DIM];   // w1 rows 64..127
    __shared__ float sT[DIM * DIM];   // wt
    __shared__ float sb1[DIM], sbt[DIM];

    int tid = threadIdx.x;
    for (int i = tid; i < DIM * DIM; i += blockDim.x) {
        sA[i] = w1[i];
        sB[i] = w1[DIM * DIM + i];
        sT[i] = wt[i];
    }
    if (tid < DIM) { sb1[tid] = b1[tid]; sbt[tid] = bt[tid]; }
    __syncthreads();

    const int lane   = tid & 31;
    const int warp   = (blockIdx.x * blockDim.x + tid) >> 5;
    const int nwarps = (gridDim.x * blockDim.x) >> 5;
    const int NP = 4;   // nodes per warp pass (amortize the weight LDS)

    float2 bb1 = *(const float2*)&sb1[2 * lane];
    float2 bbt = *(const float2*)&sbt[2 * lane];

    for (int n0 = warp * NP; n0 < N; n0 += nwarps * NP) {
        int cnt = N - n0; if (cnt > NP) cnt = NP;

        float xa[NP], xb[NP];
        #pragma unroll
        for (int j = 0; j < NP; j++) {
            int n = n0 + j;
            if (j < cnt) {
                xa[j] = x[(size_t)n * DIM + lane];
                xb[j] = x[(size_t)n * DIM + 32 + lane];
            } else { xa[j] = 0.f; xb[j] = 0.f; }
        }

        float2 au[NP], av[NP], at[NP];
        #pragma unroll
        for (int j = 0; j < NP; j++) {
            au[j] = bb1;
            av[j] = make_float2(0.f, 0.f);
            at[j] = bbt;
        }

        #pragma unroll 4
        for (int k = 0; k < DIM; k++) {
            float2 wa = *(const float2*)&sA[k * DIM + 2 * lane];
            float2 wb = *(const float2*)&sB[k * DIM + 2 * lane];
            float2 wt2 = *(const float2*)&sT[k * DIM + 2 * lane];
            #pragma unroll
            for (int j = 0; j < NP; j++) {
                float xk = (k < 32) ? __shfl_sync(0xffffffffu, xa[j], k)
                                    : __shfl_sync(0xffffffffu, xb[j], k - 32);
                au[j].x = fmaf(xk, wa.x,  au[j].x);
                au[j].y = fmaf(xk, wa.y,  au[j].y);
                av[j].x = fmaf(xk, wb.x,  av[j].x);
                av[j].y = fmaf(xk, wb.y,  av[j].y);
                at[j].x = fmaf(xk, wt2.x, at[j].x);
                at[j].y = fmaf(xk, wt2.y, at[j].y);
            }
        }

        #pragma unroll
        for (int j = 0; j < NP; j++) {
            if (j < cnt) {
                size_t base = (size_t)(n0 + j) * DIM + 2 * lane;
                *(float2*)&g_u [base] = au[j];
                *(float2*)&g_v [base] = av[j];
                *(float2*)&g_xt[base] = at[j];
            }
        }
    }
}

// ---------------------------------------------------------------------------
// Per-edge: h = relu(u[src] + v[dst] + len*w1c), w = sigmoid(h.w2 + b2),
//           out[dst] += xt[src] * w  (vector red), ew[e] = w.
// HALF-warp per edge; lane sub (0..15) owns cols 4*sub..4*sub+3 (float4).
// Scatter uses red.global.add.v4.f32 -> 16 vector REDs per edge (vs 64 scalar).
// ---------------------------------------------------------------------------
__global__ void edge_kernel(const int* __restrict__ ei,
                            const float* __restrict__ pos,
                            const float* __restrict__ w1,
                            const float* __restrict__ w2,
                            const float* __restrict__ b2p,
                            float* __restrict__ out,
                            float* __restrict__ ew,
                            int E) {
    const int lane  = threadIdx.x & 31;
    const int half  = lane >> 4;          // 0 or 1: which edge of the pair
    const int sub   = lane & 15;          // lane within half-warp
    const int warp  = (blockIdx.x * blockDim.x + threadIdx.x) >> 5;
    const int nwarps = (gridDim.x * blockDim.x) >> 5;

    // per-lane constants (cols 4*sub .. 4*sub+3)
    const float4 wc  = *(const float4*)&w1[128 * DIM + 4 * sub]; // w1 row 128 (edge_length)
    const float4 w2v = *(const float4*)&w2[4 * sub];
    const float  b2  = b2p[0];

    for (int e0 = warp * 2; e0 < E; e0 += nwarps * 2) {
        int e = e0 + half;
        bool valid = (e < E);
        int s = valid ? ei[e]     : 0;
        int d = valid ? ei[E + e] : 0;

        float dx = pos[d * 3 + 0] - pos[s * 3 + 0];
        float dy = pos[d * 3 + 1] - pos[s * 3 + 1];
        float dz = pos[d * 3 + 2] - pos[s * 3 + 2];
        float len = sqrtf(dx * dx + dy * dy + dz * dz);

        const float4 uu = *(const float4*)&g_u[(size_t)s * DIM + 4 * sub];
        const float4 vv = *(const float4*)&g_v[(size_t)d * DIM + 4 * sub];

        float h0 = fmaxf(fmaf(len, wc.x, uu.x + vv.x), 0.f);
        float h1 = fmaxf(fmaf(len, wc.y, uu.y + vv.y), 0.f);
        float h2 = fmaxf(fmaf(len, wc.z, uu.z + vv.z), 0.f);
        float h3 = fmaxf(fmaf(len, wc.w, uu.w + vv.w), 0.f);
        float p  = fmaf(h0, w2v.x, fmaf(h1, w2v.y, fmaf(h2, w2v.z, h3 * w2v.w)));

        // reduce over the 16 lanes of this half-warp (xor offsets stay in-half)
        #pragma unroll
        for (int o = 8; o > 0; o >>= 1)
            p += __shfl_xor_sync(0xffffffffu, p, o);

        float w = 1.f / (1.f + __expf(-(p + b2)));

        if (valid) {
            if (sub == 0 && ew) ew[e] = w;

            const float4 m = *(const float4*)&g_xt[(size_t)s * DIM + 4 * sub];
            float* o0 = &out[(size_t)d * DIM + 4 * sub];
            asm volatile("red.global.add.v4.f32 [%0], {%1, %2, %3, %4};"
                         :: "l"(o0), "f"(m.x * w), "f"(m.y * w),
                            "f"(m.z * w), "f"(m.w * w)
                         : "memory");
        }
    }
}

// ---------------------------------------------------------------------------
extern "C" void kernel_launch(void* const* d_in, const int* in_sizes, int n_in,
                              void* d_out, int out_size) {
    const float* x   = (const float*)d_in[0];
    const int*   ei  = (const int*)d_in[1];    // int32 (JAX x64 disabled)
    const float* pos = (const float*)d_in[2];
    const float* w1  = (const float*)d_in[3];
    const float* b1  = (const float*)d_in[4];
    const float* w2  = (const float*)d_in[5];
    const float* b2  = (const float*)d_in[6];
    const float* wt  = (const float*)d_in[7];
    const float* bt  = (const float*)d_in[8];

    int N = in_sizes[0] / DIM;   // 100000
    int E = in_sizes[1] / 2;     // 1600000

    float* out = (float*)d_out;
    // Output layout: node output [N*64] followed by edge_weights [E]
    float* ew = (out_size >= N * DIM + E) ? out + (size_t)N * DIM : nullptr;

    zero_kernel<<<592, 256>>>((float4*)out, N * DIM / 4);
    node_kernel<<<592, 256>>>(x, w1, b1, wt, bt, N);
    edge_kernel<<<2368, 256>>>(ei, pos, w1, w2, b2, out, ew, E);
}

// round 7
// speedup vs baseline: 1.5113x; 1.0884x over previous
#include <cuda_runtime.h>
#include <cuda_fp16.h>
#include <math.h>
#include <stdint.h>

// Scratch (static device arrays — no allocation allowed)
#define NMAX 100000
#define DIM  64
// Per-node src record: 64 halfs of u (x@W1a + b1) followed by 64 halfs of xt
// (x@wt + bt). 256 B contiguous -> one gather stream for src-side data.
__device__ __half g_s[NMAX * 2 * DIM];
// Per-node dst record: 64 halfs of v (x@W1b). 128 B.
__device__ __half g_d[NMAX * DIM];

// ---------------------------------------------------------------------------
// Zero the node-output region (d_out is poisoned with 0xAA).
// ---------------------------------------------------------------------------
__global__ void zero_kernel(float4* __restrict__ out, int n4) {
    int i = blockIdx.x * blockDim.x + threadIdx.x;
    int stride = gridDim.x * blockDim.x;
    float4 z = make_float4(0.f, 0.f, 0.f, 0.f);
    for (; i < n4; i += stride) out[i] = z;
}

// ---------------------------------------------------------------------------
// Per-node precompute: u = x@W1a + b1, v = x@W1b, xt = x@wt + bt  (fp32 math,
// fp16 storage). Warp per NP nodes; weights staged in shared. Each lane owns
// output cols (2*lane, 2*lane+1).
// ---------------------------------------------------------------------------
__global__ void node_kernel(const float* __restrict__ x,
                            const float* __restrict__ w1,
                            const float* __restrict__ b1,
                            const float* __restrict__ wt,
                            const float* __restrict__ bt,
                            int N) {
    __shared__ float sA[DIM * DIM];   // w1 rows 0..63
    __shared__ float sB[DIM * DIM];   // w1 rows 64..127
    __shared__ float sT[DIM * DIM];   // wt
    __shared__ float sb1[DIM], sbt[DIM];

    int tid = threadIdx.x;
    for (int i = tid; i < DIM * DIM; i += blockDim.x) {
        sA[i] = w1[i];
        sB[i] = w1[DIM * DIM + i];
        sT[i] = wt[i];
    }
    if (tid < DIM) { sb1[tid] = b1[tid]; sbt[tid] = bt[tid]; }
    __syncthreads();

    const int lane   = tid & 31;
    const int warp   = (blockIdx.x * blockDim.x + tid) >> 5;
    const int nwarps = (gridDim.x * blockDim.x) >> 5;
    const int NP = 4;   // nodes per warp pass (amortize the weight LDS)

    float2 bb1 = *(const float2*)&sb1[2 * lane];
    float2 bbt = *(const float2*)&sbt[2 * lane];

    for (int n0 = warp * NP; n0 < N; n0 += nwarps * NP) {
        int cnt = N - n0; if (cnt > NP) cnt = NP;

        float xa[NP], xb[NP];
        #pragma unroll
        for (int j = 0; j < NP; j++) {
            int n = n0 + j;
            if (j < cnt) {
                xa[j] = x[(size_t)n * DIM + lane];
                xb[j] = x[(size_t)n * DIM + 32 + lane];
            } else { xa[j] = 0.f; xb[j] = 0.f; }
        }

        float2 au[NP], av[NP], at[NP];
        #pragma unroll
        for (int j = 0; j < NP; j++) {
            au[j] = bb1;
            av[j] = make_float2(0.f, 0.f);
            at[j] = bbt;
        }

        #pragma unroll 4
        for (int k = 0; k < DIM; k++) {
            float2 wa = *(const float2*)&sA[k * DIM + 2 * lane];
            float2 wb = *(const float2*)&sB[k * DIM + 2 * lane];
            float2 wt2 = *(const float2*)&sT[k * DIM + 2 * lane];
            #pragma unroll
            for (int j = 0; j < NP; j++) {
                float xk = (k < 32) ? __shfl_sync(0xffffffffu, xa[j], k)
                                    : __shfl_sync(0xffffffffu, xb[j], k - 32);
                au[j].x = fmaf(xk, wa.x,  au[j].x);
                au[j].y = fmaf(xk, wa.y,  au[j].y);
                av[j].x = fmaf(xk, wb.x,  av[j].x);
                av[j].y = fmaf(xk, wb.y,  av[j].y);
                at[j].x = fmaf(xk, wt2.x, at[j].x);
                at[j].y = fmaf(xk, wt2.y, at[j].y);
            }
        }

        #pragma unroll
        for (int j = 0; j < NP; j++) {
            if (j < cnt) {
                size_t n = (size_t)(n0 + j);
                *(__half2*)&g_s[n * 2 * DIM + 2 * lane]       = __float22half2_rn(au[j]);
                *(__half2*)&g_s[n * 2 * DIM + DIM + 2 * lane] = __float22half2_rn(at[j]);
                *(__half2*)&g_d[n * DIM + 2 * lane]           = __float22half2_rn(av[j]);
            }
        }
    }
}

// ---------------------------------------------------------------------------
// Per-edge: h = relu(u[src] + v[dst] + len*w1c), w = sigmoid(h.w2 + b2),
//           out[dst] += xt[src] * w  (red.v4), ew[e] = w.
// HALF-warp per edge; lane sub (0..15) owns cols 4*sub..4*sub+3.
// Tables are fp16 (u,xt packed per src node; v per dst node).
// ---------------------------------------------------------------------------
__global__ void edge_kernel(const int* __restrict__ ei,
                            const float* __restrict__ pos,
                            const float* __restrict__ w1,
                            const float* __restrict__ w2,
                            const float* __restrict__ b2p,
                            float* __restrict__ out,
                            float* __restrict__ ew,
                            int E) {
    const int lane  = threadIdx.x & 31;
    const int half  = lane >> 4;          // 0 or 1: which edge of the pair
    const int sub   = lane & 15;          // lane within half-warp
    const int warp  = (blockIdx.x * blockDim.x + threadIdx.x) >> 5;
    const int nwarps = (gridDim.x * blockDim.x) >> 5;

    // per-lane constants (cols 4*sub .. 4*sub+3)
    const float4 wc  = *(const float4*)&w1[128 * DIM + 4 * sub]; // w1 row 128 (edge_length)
    const float4 w2v = *(const float4*)&w2[4 * sub];
    const float  b2  = b2p[0];

    for (int e0 = warp * 2; e0 < E; e0 += nwarps * 2) {
        int e = e0 + half;
        bool valid = (e < E);
        int s = valid ? ei[e]     : 0;
        int d = valid ? ei[E + e] : 0;

        float dx = pos[d * 3 + 0] - pos[s * 3 + 0];
        float dy = pos[d * 3 + 1] - pos[s * 3 + 1];
        float dz = pos[d * 3 + 2] - pos[s * 3 + 2];
        float len = sqrtf(dx * dx + dy * dy + dz * dz);

        // src record: u at [0,64), xt at [64,128) halfs
        const __half2* sp = (const __half2*)&g_s[(size_t)s * 2 * DIM + 4 * sub];
        const __half2* xp = (const __half2*)&g_s[(size_t)s * 2 * DIM + DIM + 4 * sub];
        const __half2* vp = (const __half2*)&g_d[(size_t)d * DIM + 4 * sub];

        uint2 uraw = *(const uint2*)sp;
        uint2 vraw = *(const uint2*)vp;
        float2 u0 = __half22float2(*(const __half2*)&uraw.x);
        float2 u1 = __half22float2(*(const __half2*)&uraw.y);
        float2 v0 = __half22float2(*(const __half2*)&vraw.x);
        float2 v1 = __half22float2(*(const __half2*)&vraw.y);

        float h0 = fmaxf(fmaf(len, wc.x, u0.x + v0.x), 0.f);
        float h1 = fmaxf(fmaf(len, wc.y, u0.y + v0.y), 0.f);
        float h2 = fmaxf(fmaf(len, wc.z, u1.x + v1.x), 0.f);
        float h3 = fmaxf(fmaf(len, wc.w, u1.y + v1.y), 0.f);
        float p  = fmaf(h0, w2v.x, fmaf(h1, w2v.y, fmaf(h2, w2v.z, h3 * w2v.w)));

        // reduce over the 16 lanes of this half-warp (xor offsets stay in-half)
        #pragma unroll
        for (int o = 8; o > 0; o >>= 1)
            p += __shfl_xor_sync(0xffffffffu, p, o);

        float w = 1.f / (1.f + __expf(-(p + b2)));

        if (valid) {
            if (sub == 0 && ew) ew[e] = w;

            uint2 mraw = *(const uint2*)xp;
            float2 m0 = __half22float2(*(const __half2*)&mraw.x);
            float2 m1 = __half22float2(*(const __half2*)&mraw.y);

            float* o0 = &out[(size_t)d * DIM + 4 * sub];
            asm volatile("red.global.add.v4.f32 [%0], {%1, %2, %3, %4};"
                         :: "l"(o0), "f"(m0.x * w), "f"(m0.y * w),
                            "f"(m1.x * w), "f"(m1.y * w)
                         : "memory");
        }
    }
}

// ---------------------------------------------------------------------------
extern "C" void kernel_launch(void* const* d_in, const int* in_sizes, int n_in,
                              void* d_out, int out_size) {
    const float* x   = (const float*)d_in[0];
    const int*   ei  = (const int*)d_in[1];    // int32 (JAX x64 disabled)
    const float* pos = (const float*)d_in[2];
    const float* w1  = (const float*)d_in[3];
    const float* b1  = (const float*)d_in[4];
    const float* w2  = (const float*)d_in[5];
    const float* b2  = (const float*)d_in[6];
    const float* wt  = (const float*)d_in[7];
    const float* bt  = (const float*)d_in[8];

    int N = in_sizes[0] / DIM;   // 100000
    int E = in_sizes[1] / 2;     // 1600000

    float* out = (float*)d_out;
    // Output layout: node output [N*64] followed by edge_weights [E]
    float* ew = (out_size >= N * DIM + E) ? out + (size_t)N * DIM : nullptr;

    zero_kernel<<<592, 256>>>((float4*)out, N * DIM / 4);
    node_kernel<<<592, 256>>>(x, w1, b1, wt, bt, N);
    edge_kernel<<<2368, 256>>>(ei, pos, w1, w2, b2, out, ew, E);
}